// round 2
// baseline (speedup 1.0000x reference)
#include <cuda_runtime.h>
#include <cuda_bf16.h>

#define B_CONST 32
#define L_CONST 256
#define H_CONST 512

// Scratch (no allocations allowed anywhere)
__device__ int g_csum[B_CONST * L_CONST];
__device__ int g_total[B_CONST];

// Kernel 1: dead-simple serial cumsum, one thread per batch. Race-free by
// construction. 256 adds per thread, 32 threads total -> negligible.
__global__ void csum_kernel(const int* __restrict__ dur) {
    int b = threadIdx.x;
    if (b < B_CONST) {
        int acc = 0;
        const int* d = dur + b * L_CONST;
        int* c = g_csum + b * L_CONST;
        #pragma unroll 8
        for (int i = 0; i < L_CONST; ++i) {
            acc += d[i];
            c[i] = acc;
        }
        g_total[b] = acc;
    }
}

// Kernel 2: one block per output row (t, b), 256 threads.
// idx = searchsorted(csum, t, side='right') computed as a cooperative count
// of entries <= t (equivalent for sorted csum, duplicates included), then all
// 256 threads copy the 512-float row as float2 (or zero it when masked).
__global__ void __launch_bounds__(256) expand_kernel(
    const float* __restrict__ x,    // [B, L, H]
    float* __restrict__ out,        // [B, T, H]
    float* __restrict__ out_mask,   // [B, T] (0.0 / 1.0)
    int T)
{
    int t = blockIdx.x;
    int b = blockIdx.y;
    int lane = threadIdx.x & 31;
    int warp = threadIdx.x >> 5;

    __shared__ int s_cnt[8];
    __shared__ int s_idx;

    int tot = g_total[b];

    // count of csum entries <= t  ==  searchsorted(c, t, 'right')
    int cval = g_csum[b * L_CONST + threadIdx.x];
    unsigned ball = __ballot_sync(0xFFFFFFFFu, cval <= t);
    if (lane == 0) s_cnt[warp] = __popc(ball);
    __syncthreads();
    if (threadIdx.x == 0) {
        int idx = s_cnt[0] + s_cnt[1] + s_cnt[2] + s_cnt[3]
                + s_cnt[4] + s_cnt[5] + s_cnt[6] + s_cnt[7];
        if (idx > L_CONST - 1) idx = L_CONST - 1;   // jnp.clip(idx, 0, L-1)
        s_idx = idx;
        out_mask[(size_t)b * T + t] = (t < tot) ? 1.0f : 0.0f;
    }
    __syncthreads();

    float2* dst = reinterpret_cast<float2*>(out + ((size_t)b * T + t) * H_CONST);
    if (t < tot) {
        const float2* src = reinterpret_cast<const float2*>(
            x + ((size_t)b * L_CONST + s_idx) * H_CONST);
        dst[threadIdx.x] = src[threadIdx.x];
    } else {
        dst[threadIdx.x] = make_float2(0.f, 0.f);
    }
}

extern "C" void kernel_launch(void* const* d_in, const int* in_sizes, int n_in,
                              void* d_out, int out_size) {
    // Robust input binding: x has B*L*H = 4,194,304 elements, durations 8,192.
    const float* x;
    const int*   dur;
    if (in_sizes[0] == B_CONST * L_CONST) {
        dur = (const int*)d_in[0];
        x   = (const float*)d_in[1];
    } else {
        x   = (const float*)d_in[0];
        dur = (const int*)d_in[1];
    }

    // Output: [B,T,H] f32 outputs followed by [B,T] mask, one flat buffer.
    int T = out_size / (B_CONST * (H_CONST + 1));

    float* out      = (float*)d_out;
    float* out_mask = out + (size_t)B_CONST * T * H_CONST;

    csum_kernel<<<1, 32>>>(dur);

    dim3 grid(T, B_CONST);
    expand_kernel<<<grid, 256>>>(x, out, out_mask, T);
}

// round 3
// speedup vs baseline: 1.5129x; 1.5129x over previous
#include <cuda_runtime.h>
#include <cuda_bf16.h>

#define B_CONST 32
#define L_CONST 256
#define H_CONST 512
#define T_MAX   8192   // durations < 16, L=256 -> total < 4096; headroom

// Scratch (no allocations allowed anywhere)
__device__ int g_idx[B_CONST * T_MAX];   // source index per output frame, -1 = masked

// Kernel 1: per-batch scan + scatter of the index table + mask write.
// Block b: thread 0 serially scans 256 durations into shared (trivial work),
// then every thread l scatters its own repeat range [csum[l-1], csum[l]) with
// value l, and the tail [total, T) with -1. Mask written here as 0.0/1.0.
__global__ void __launch_bounds__(L_CONST) build_idx_kernel(
    const int* __restrict__ dur,
    float* __restrict__ out_mask,   // [B, T]
    int T)
{
    __shared__ int s_csum[L_CONST];
    int b = blockIdx.x;
    int l = threadIdx.x;

    if (l == 0) {
        int acc = 0;
        const int* d = dur + b * L_CONST;
        #pragma unroll 8
        for (int i = 0; i < L_CONST; ++i) {
            acc += d[i];
            s_csum[i] = acc;
        }
    }
    __syncthreads();

    int end   = s_csum[l];
    int start = (l == 0) ? 0 : s_csum[l - 1];
    int total = s_csum[L_CONST - 1];

    int* idx = g_idx + b * T_MAX;
    for (int t = start; t < end; ++t) idx[t] = l;

    // tail: masked-out frames
    for (int t = total + l; t < T; t += L_CONST) idx[t] = -1;

    // mask
    float* m = out_mask + (size_t)b * T;
    for (int t = l; t < T; t += L_CONST) m[t] = (t < total) ? 1.0f : 0.0f;
}

// Kernel 2: pure streaming gather-copy. One thread per float4 of output.
// grid: (ceil(T*128/256), B). No shared, no syncs.
__global__ void __launch_bounds__(256) expand_kernel(
    const float4* __restrict__ x4,   // [B, L, 128]
    float4* __restrict__ out4,       // [B, T, 128]
    int T)
{
    int tid = blockIdx.x * 256 + threadIdx.x;      // over T*128
    int b   = blockIdx.y;
    int t   = tid >> 7;                            // H/4 = 128 float4 per row
    if (t >= T) return;
    int j   = tid & 127;

    int idx = g_idx[b * T_MAX + t];

    float4 v;
    if (idx >= 0) {
        v = x4[((size_t)b * L_CONST + idx) * 128 + j];
    } else {
        v = make_float4(0.f, 0.f, 0.f, 0.f);
    }
    out4[((size_t)b * T + t) * 128 + j] = v;
}

extern "C" void kernel_launch(void* const* d_in, const int* in_sizes, int n_in,
                              void* d_out, int out_size) {
    const float* x;
    const int*   dur;
    if (in_sizes[0] == B_CONST * L_CONST) {
        dur = (const int*)d_in[0];
        x   = (const float*)d_in[1];
    } else {
        x   = (const float*)d_in[0];
        dur = (const int*)d_in[1];
    }

    int T = out_size / (B_CONST * (H_CONST + 1));

    float* out      = (float*)d_out;
    float* out_mask = out + (size_t)B_CONST * T * H_CONST;

    build_idx_kernel<<<B_CONST, L_CONST>>>(dur, out_mask, T);

    int elems_per_batch = T * (H_CONST / 4);           // float4 count per batch
    dim3 grid((elems_per_batch + 255) / 256, B_CONST);
    expand_kernel<<<grid, 256>>>(
        (const float4*)x, (float4*)out, T);
}

// round 4
// speedup vs baseline: 2.5600x; 1.6921x over previous
#include <cuda_runtime.h>
#include <cuda_bf16.h>

#define B_CONST 32
#define L_CONST 256
#define H_CONST 512
#define T_MAX   8192   // durations < 16, L=256 -> total < 4096; headroom

// Scratch (no allocations allowed anywhere)
__device__ int g_idx[B_CONST * T_MAX];   // source index per output frame, -1 = masked

// Kernel 1: per-batch parallel scan + scatter of the index table + mask write.
__global__ void __launch_bounds__(L_CONST) build_idx_kernel(
    const int* __restrict__ dur,
    float* __restrict__ out_mask,   // [B, T]
    int T)
{
    __shared__ int s_wsum[8];
    __shared__ int s_total;

    int b    = blockIdx.x;
    int l    = threadIdx.x;
    int lane = l & 31;
    int w    = l >> 5;

    int d = dur[b * L_CONST + l];

    // warp inclusive scan
    int v = d;
    #pragma unroll
    for (int off = 1; off < 32; off <<= 1) {
        int n = __shfl_up_sync(0xFFFFFFFFu, v, off);
        if (lane >= off) v += n;
    }
    if (lane == 31) s_wsum[w] = v;
    __syncthreads();

    // scan the 8 warp sums in warp 0
    if (w == 0) {
        int ws = (lane < 8) ? s_wsum[lane] : 0;
        #pragma unroll
        for (int off = 1; off < 8; off <<= 1) {
            int n = __shfl_up_sync(0xFFFFFFFFu, ws, off);
            if (lane >= off) ws += n;
        }
        if (lane < 8) s_wsum[lane] = ws;
        if (lane == 7) s_total = ws;
    }
    __syncthreads();

    int base = (w > 0) ? s_wsum[w - 1] : 0;
    int end   = base + v;        // inclusive csum[l]
    int start = end - d;
    int total = s_total;

    int* idx = g_idx + b * T_MAX;
    for (int t = start; t < end; ++t) idx[t] = l;

    // tail sentinel for masked frames
    for (int t = total + l; t < T; t += L_CONST) idx[t] = -1;

    // mask 0.0/1.0
    float* m = out_mask + (size_t)b * T;
    for (int t = l; t < T; t += L_CONST) m[t] = (t < total) ? 1.0f : 0.0f;
}

// Kernel 2: streaming gather-copy, one WARP per output row, 4 float4 per
// thread (j, j+32, j+64, j+96) -> 4 independent LDG.128 in flight (MLP=4).
__global__ void __launch_bounds__(256) expand_kernel(
    const float4* __restrict__ x4,   // [B, L, 128]
    float4* __restrict__ out4,       // [B, T, 128]
    int T)
{
    int tid = blockIdx.x * 256 + threadIdx.x;   // over T*32 per batch
    int b   = blockIdx.y;
    int t   = tid >> 5;
    if (t >= T) return;
    int j   = tid & 31;

    int idx = g_idx[b * T_MAX + t];             // warp-uniform, L1 broadcast

    float4* dst = out4 + ((size_t)b * T + t) * 128 + j;

    if (idx >= 0) {
        const float4* src = x4 + ((size_t)b * L_CONST + idx) * 128 + j;
        float4 v0 = src[0];
        float4 v1 = src[32];
        float4 v2 = src[64];
        float4 v3 = src[96];
        dst[0]  = v0;
        dst[32] = v1;
        dst[64] = v2;
        dst[96] = v3;
    } else {
        float4 z = make_float4(0.f, 0.f, 0.f, 0.f);
        dst[0]  = z;
        dst[32] = z;
        dst[64] = z;
        dst[96] = z;
    }
}

extern "C" void kernel_launch(void* const* d_in, const int* in_sizes, int n_in,
                              void* d_out, int out_size) {
    const float* x;
    const int*   dur;
    if (in_sizes[0] == B_CONST * L_CONST) {
        dur = (const int*)d_in[0];
        x   = (const float*)d_in[1];
    } else {
        x   = (const float*)d_in[0];
        dur = (const int*)d_in[1];
    }

    int T = out_size / (B_CONST * (H_CONST + 1));

    float* out      = (float*)d_out;
    float* out_mask = out + (size_t)B_CONST * T * H_CONST;

    build_idx_kernel<<<B_CONST, L_CONST>>>(dur, out_mask, T);

    int threads_per_batch = T * 32;              // one warp per row
    dim3 grid((threads_per_batch + 255) / 256, B_CONST);
    expand_kernel<<<grid, 256>>>(
        (const float4*)x, (float4*)out, T);
}

// round 5
// speedup vs baseline: 2.9705x; 1.1604x over previous
#include <cuda_runtime.h>
#include <cuda_bf16.h>

#define B_CONST 32
#define L_CONST 256
#define H_CONST 512
#define T_MAX   8192   // durations < 16, L=256 -> total < 4096; headroom

// Scratch (no allocations allowed anywhere)
__device__ int g_idx[B_CONST * T_MAX];   // source index per output frame, -1 = masked

// Kernel 1: per-batch parallel scan + scatter of the index table + mask write.
__global__ void __launch_bounds__(L_CONST) build_idx_kernel(
    const int* __restrict__ dur,
    float* __restrict__ out_mask,   // [B, T]
    int T)
{
    __shared__ int s_wsum[8];
    __shared__ int s_total;

    int b    = blockIdx.x;
    int l    = threadIdx.x;
    int lane = l & 31;
    int w    = l >> 5;

    int d = dur[b * L_CONST + l];

    // warp inclusive scan
    int v = d;
    #pragma unroll
    for (int off = 1; off < 32; off <<= 1) {
        int n = __shfl_up_sync(0xFFFFFFFFu, v, off);
        if (lane >= off) v += n;
    }
    if (lane == 31) s_wsum[w] = v;
    __syncthreads();

    // scan the 8 warp sums in warp 0
    if (w == 0) {
        int ws = (lane < 8) ? s_wsum[lane] : 0;
        #pragma unroll
        for (int off = 1; off < 8; off <<= 1) {
            int n = __shfl_up_sync(0xFFFFFFFFu, ws, off);
            if (lane >= off) ws += n;
        }
        if (lane < 8) s_wsum[lane] = ws;
        if (lane == 7) s_total = ws;
    }
    __syncthreads();

    int base = (w > 0) ? s_wsum[w - 1] : 0;
    int end   = base + v;        // inclusive csum[l]
    int start = end - d;
    int total = s_total;

    int* idx = g_idx + b * T_MAX;
    for (int t = start; t < end; ++t) idx[t] = l;

    // tail sentinel for masked frames
    for (int t = total + l; t < T; t += L_CONST) idx[t] = -1;

    // mask 0.0/1.0
    float* m = out_mask + (size_t)b * T;
    for (int t = l; t < T; t += L_CONST) m[t] = (t < total) ? 1.0f : 0.0f;
}

// Kernel 2: streaming gather-copy. One WARP per TWO output rows.
// Each thread: 4 float4 per row x 2 rows = 8 independent LDG.128 front-batched
// (MLP=8), then 8 streaming STG.128 (__stcs -> keep x resident in L2).
__global__ void __launch_bounds__(256) expand_kernel(
    const float4* __restrict__ x4,   // [B, L, 128]
    float4* __restrict__ out4,       // [B, T, 128]
    int T)
{
    int wid  = (blockIdx.x * 256 + threadIdx.x) >> 5;  // warp id over ceil(T/2) per batch
    int lane = threadIdx.x & 31;
    int b    = blockIdx.y;

    int t0 = wid * 2;
    if (t0 >= T) return;
    int t1 = t0 + 1;
    bool has_t1 = (t1 < T);

    int idx0 = g_idx[b * T_MAX + t0];                  // warp-uniform
    int idx1 = has_t1 ? g_idx[b * T_MAX + t1] : -1;

    const float4 z = make_float4(0.f, 0.f, 0.f, 0.f);
    float4 v0 = z, v1 = z, v2 = z, v3 = z;
    float4 u0 = z, u1 = z, u2 = z, u3 = z;

    if (idx0 >= 0) {
        const float4* s = x4 + ((size_t)b * L_CONST + idx0) * 128 + lane;
        v0 = __ldg(s);
        v1 = __ldg(s + 32);
        v2 = __ldg(s + 64);
        v3 = __ldg(s + 96);
    }
    if (idx1 >= 0) {
        const float4* s = x4 + ((size_t)b * L_CONST + idx1) * 128 + lane;
        u0 = __ldg(s);
        u1 = __ldg(s + 32);
        u2 = __ldg(s + 64);
        u3 = __ldg(s + 96);
    }

    float4* d0 = out4 + ((size_t)b * T + t0) * 128 + lane;
    __stcs(d0,      v0);
    __stcs(d0 + 32, v1);
    __stcs(d0 + 64, v2);
    __stcs(d0 + 96, v3);

    if (has_t1) {
        float4* d1 = d0 + 128;
        __stcs(d1,      u0);
        __stcs(d1 + 32, u1);
        __stcs(d1 + 64, u2);
        __stcs(d1 + 96, u3);
    }
}

extern "C" void kernel_launch(void* const* d_in, const int* in_sizes, int n_in,
                              void* d_out, int out_size) {
    const float* x;
    const int*   dur;
    if (in_sizes[0] == B_CONST * L_CONST) {
        dur = (const int*)d_in[0];
        x   = (const float*)d_in[1];
    } else {
        x   = (const float*)d_in[0];
        dur = (const int*)d_in[1];
    }

    int T = out_size / (B_CONST * (H_CONST + 1));

    float* out      = (float*)d_out;
    float* out_mask = out + (size_t)B_CONST * T * H_CONST;

    build_idx_kernel<<<B_CONST, L_CONST>>>(dur, out_mask, T);

    int warps_per_batch   = (T + 1) / 2;          // one warp per 2 rows
    int threads_per_batch = warps_per_batch * 32;
    dim3 grid((threads_per_batch + 255) / 256, B_CONST);
    expand_kernel<<<grid, 256>>>(
        (const float4*)x, (float4*)out, T);
}